// round 1
// baseline (speedup 1.0000x reference)
#include <cuda_runtime.h>
#include <cuda_bf16.h>
#include <math.h>

// ---------------------------------------------------------------------------
// Problem constants
// ---------------------------------------------------------------------------
#define BB   4
#define SS   1024
#define DD   1024
#define HH   16
#define HD   64
#define FFD  4096
#define NT   (BB*SS)          // 4096 tokens
#define INV_SCALE 0.125f      // 1/sqrt(64)
#define LAM_EFF   0.5f        // LAMBDA_MIN + (MAX-MIN)*... == 0.5 exactly

// ---------------------------------------------------------------------------
// Scratch (device globals; no runtime allocation allowed)
// ---------------------------------------------------------------------------
__device__ float buf_xn  [NT*DD];     // LN output (attn pre-norm, then FFN pre-norm)
__device__ float buf_Q   [NT*DD];
__device__ float buf_K   [NT*DD];
__device__ float buf_tK  [NT*DD];     // tanh(K)
__device__ float buf_V   [NT*DD];
__device__ float buf_tQJ [NT*DD];     // tanh(Q) @ J  per head
__device__ float buf_ao  [NT*DD];     // attention output (pre out-proj)
__device__ float buf_x1  [NT*DD];     // x + attn  (residual stream)
__device__ float buf_th  [NT*DD];     // tanh(LN_ffn(x1))
__device__ float buf_hhat[NT*FFD];    // QBNN h_hat scratch (layer1: full, layer2: first NT*DD)
__device__ float buf_h1  [NT*FFD];    // gelu(LN(hhat1))
__device__ float buf_th1 [NT*FFD];    // tanh(h1)

// ---------------------------------------------------------------------------
// LayerNorm: one block per row
// ---------------------------------------------------------------------------
__global__ void __launch_bounds__(256) ln_kernel(
    const float* __restrict__ X, const float* __restrict__ g,
    const float* __restrict__ b, float* __restrict__ Y,
    float* __restrict__ YT, int N)
{
    int row = blockIdx.x;
    const float* x = X + (size_t)row * N;
    float s = 0.f, s2 = 0.f;
    for (int i = threadIdx.x; i < N; i += 256) {
        float v = x[i];
        s += v; s2 = fmaf(v, v, s2);
    }
    __shared__ float sh[64];
    for (int o = 16; o > 0; o >>= 1) {
        s  += __shfl_down_sync(0xffffffffu, s,  o);
        s2 += __shfl_down_sync(0xffffffffu, s2, o);
    }
    int wid = threadIdx.x >> 5, lane = threadIdx.x & 31;
    if (lane == 0) { sh[wid] = s; sh[wid + 32] = s2; }
    __syncthreads();
    if (threadIdx.x == 0) {
        float ts = 0.f, ts2 = 0.f;
        for (int w = 0; w < 8; w++) { ts += sh[w]; ts2 += sh[w + 32]; }
        float mu  = ts / N;
        float var = ts2 / N - mu * mu;
        sh[0] = mu; sh[1] = rsqrtf(var + 1e-5f);
    }
    __syncthreads();
    float mu = sh[0], rstd = sh[1];
    for (int i = threadIdx.x; i < N; i += 256) {
        float v = (x[i] - mu) * rstd * g[i] + b[i];
        Y[(size_t)row * N + i] = v;
        if (YT) YT[(size_t)row * N + i] = tanhf(v);
    }
}

// ---------------------------------------------------------------------------
// LayerNorm + exact GELU (+ optional residual add, optional tanh side-output)
// ---------------------------------------------------------------------------
__global__ void __launch_bounds__(256) ln_gelu_kernel(
    const float* __restrict__ X, const float* __restrict__ g,
    const float* __restrict__ b, const float* __restrict__ Res,
    float* __restrict__ Y, float* __restrict__ YT, int N)
{
    int row = blockIdx.x;
    const float* x = X + (size_t)row * N;
    float s = 0.f, s2 = 0.f;
    for (int i = threadIdx.x; i < N; i += 256) {
        float v = x[i];
        s += v; s2 = fmaf(v, v, s2);
    }
    __shared__ float sh[64];
    for (int o = 16; o > 0; o >>= 1) {
        s  += __shfl_down_sync(0xffffffffu, s,  o);
        s2 += __shfl_down_sync(0xffffffffu, s2, o);
    }
    int wid = threadIdx.x >> 5, lane = threadIdx.x & 31;
    if (lane == 0) { sh[wid] = s; sh[wid + 32] = s2; }
    __syncthreads();
    if (threadIdx.x == 0) {
        float ts = 0.f, ts2 = 0.f;
        for (int w = 0; w < 8; w++) { ts += sh[w]; ts2 += sh[w + 32]; }
        float mu  = ts / N;
        float var = ts2 / N - mu * mu;
        sh[0] = mu; sh[1] = rsqrtf(var + 1e-5f);
    }
    __syncthreads();
    float mu = sh[0], rstd = sh[1];
    for (int i = threadIdx.x; i < N; i += 256) {
        float v  = (x[i] - mu) * rstd * g[i] + b[i];
        float ge = v * normcdff(v);              // exact GELU: v * Phi(v)
        float out = Res ? Res[(size_t)row * N + i] + ge : ge;
        Y[(size_t)row * N + i] = out;
        if (YT) YT[(size_t)row * N + i] = tanhf(ge);
    }
}

// ---------------------------------------------------------------------------
// Plain GEMM: C = A[M,K] @ B[K,N] + bias (+ Res), optional tanh side-output.
// BM=128, BN=64, BK=16, 256 threads, 8x4 microtile.
// ---------------------------------------------------------------------------
template<bool RES, bool TOUT>
__global__ void __launch_bounds__(256) gemm_kernel(
    const float* __restrict__ A, const float* __restrict__ Bm,
    const float* __restrict__ bias, const float* __restrict__ Res,
    float* __restrict__ C, float* __restrict__ CT,
    int M, int N, int K)
{
    __shared__ __align__(16) float As[16][128];
    __shared__ __align__(16) float Bs[16][64];
    int tid = threadIdx.x;
    int bn = blockIdx.x << 6, bm = blockIdx.y << 7;
    int tx = tid & 15, ty = tid >> 4;
    float c[8][4] = {};

    for (int k0 = 0; k0 < K; k0 += 16) {
        #pragma unroll
        for (int i = 0; i < 2; i++) {
            int idx = (tid << 1) + i;
            int ar = idx >> 2, kq = (idx & 3) << 2;
            float4 v = *(const float4*)&A[(size_t)(bm + ar) * K + k0 + kq];
            As[kq + 0][ar] = v.x; As[kq + 1][ar] = v.y;
            As[kq + 2][ar] = v.z; As[kq + 3][ar] = v.w;
        }
        {
            int kk = tid >> 4, nq = (tid & 15) << 2;
            *(float4*)&Bs[kk][nq] = *(const float4*)&Bm[(size_t)(k0 + kk) * N + bn + nq];
        }
        __syncthreads();
        #pragma unroll
        for (int kk = 0; kk < 16; kk++) {
            float a[8], bv[4];
            *(float4*)&a[0] = *(const float4*)&As[kk][ty * 8];
            *(float4*)&a[4] = *(const float4*)&As[kk][ty * 8 + 4];
            *(float4*)&bv[0] = *(const float4*)&Bs[kk][tx * 4];
            #pragma unroll
            for (int i = 0; i < 8; i++)
                #pragma unroll
                for (int j = 0; j < 4; j++)
                    c[i][j] = fmaf(a[i], bv[j], c[i][j]);
        }
        __syncthreads();
    }

    int col0 = bn + tx * 4;
    float4 b4 = *(const float4*)&bias[col0];
    #pragma unroll
    for (int i = 0; i < 8; i++) {
        int row = bm + ty * 8 + i;
        float4 v;
        v.x = c[i][0] + b4.x; v.y = c[i][1] + b4.y;
        v.z = c[i][2] + b4.z; v.w = c[i][3] + b4.w;
        if (RES) {
            float4 r = *(const float4*)&Res[(size_t)row * N + col0];
            v.x += r.x; v.y += r.y; v.z += r.z; v.w += r.w;
        }
        *(float4*)&C[(size_t)row * N + col0] = v;
        if (TOUT) {
            float4 t;
            t.x = tanhf(v.x); t.y = tanhf(v.y); t.z = tanhf(v.z); t.w = tanhf(v.w);
            *(float4*)&CT[(size_t)row * N + col0] = t;
        }
    }
}

// ---------------------------------------------------------------------------
// QBNN dual GEMM: C1 = A@B1 + bias1 ; C2 = TA@B2 ;
// Out = h_tilde + 0.5 * C2 * tanh(h_tilde),   h_tilde = C1
// ---------------------------------------------------------------------------
__global__ void __launch_bounds__(256) qbnn_gemm_kernel(
    const float* __restrict__ A,  const float* __restrict__ TA,
    const float* __restrict__ B1, const float* __restrict__ B2,
    const float* __restrict__ bias1, float* __restrict__ Out,
    int M, int N, int K)
{
    __shared__ __align__(16) float As [16][128];
    __shared__ __align__(16) float TAs[16][128];
    __shared__ __align__(16) float B1s[16][64];
    __shared__ __align__(16) float B2s[16][64];
    int tid = threadIdx.x;
    int bn = blockIdx.x << 6, bm = blockIdx.y << 7;
    int tx = tid & 15, ty = tid >> 4;
    float c1[8][4] = {}, c2[8][4] = {};

    for (int k0 = 0; k0 < K; k0 += 16) {
        #pragma unroll
        for (int i = 0; i < 2; i++) {
            int idx = (tid << 1) + i;
            int ar = idx >> 2, kq = (idx & 3) << 2;
            size_t ga = (size_t)(bm + ar) * K + k0 + kq;
            float4 v = *(const float4*)&A[ga];
            As[kq + 0][ar] = v.x; As[kq + 1][ar] = v.y;
            As[kq + 2][ar] = v.z; As[kq + 3][ar] = v.w;
            float4 w = *(const float4*)&TA[ga];
            TAs[kq + 0][ar] = w.x; TAs[kq + 1][ar] = w.y;
            TAs[kq + 2][ar] = w.z; TAs[kq + 3][ar] = w.w;
        }
        {
            int kk = tid >> 4, nq = (tid & 15) << 2;
            size_t gb = (size_t)(k0 + kk) * N + bn + nq;
            *(float4*)&B1s[kk][nq] = *(const float4*)&B1[gb];
            *(float4*)&B2s[kk][nq] = *(const float4*)&B2[gb];
        }
        __syncthreads();
        #pragma unroll
        for (int kk = 0; kk < 16; kk++) {
            float a[8], ta[8], b1v[4], b2v[4];
            *(float4*)&a[0]  = *(const float4*)&As[kk][ty * 8];
            *(float4*)&a[4]  = *(const float4*)&As[kk][ty * 8 + 4];
            *(float4*)&ta[0] = *(const float4*)&TAs[kk][ty * 8];
            *(float4*)&ta[4] = *(const float4*)&TAs[kk][ty * 8 + 4];
            *(float4*)&b1v[0] = *(const float4*)&B1s[kk][tx * 4];
            *(float4*)&b2v[0] = *(const float4*)&B2s[kk][tx * 4];
            #pragma unroll
            for (int i = 0; i < 8; i++)
                #pragma unroll
                for (int j = 0; j < 4; j++) {
                    c1[i][j] = fmaf(a[i],  b1v[j], c1[i][j]);
                    c2[i][j] = fmaf(ta[i], b2v[j], c2[i][j]);
                }
        }
        __syncthreads();
    }

    int col0 = bn + tx * 4;
    float4 b4 = *(const float4*)&bias1[col0];
    float bb[4] = { b4.x, b4.y, b4.z, b4.w };
    #pragma unroll
    for (int i = 0; i < 8; i++) {
        int row = bm + ty * 8 + i;
        float4 v;
        float* vp = &v.x;
        #pragma unroll
        for (int j = 0; j < 4; j++) {
            float ht = c1[i][j] + bb[j];
            float sr = tanhf(ht);
            vp[j] = fmaf(LAM_EFF * c2[i][j], sr, ht);
        }
        *(float4*)&Out[(size_t)row * N + col0] = v;
    }
}

// ---------------------------------------------------------------------------
// tQJ: per (b,h): tanh(Q[b,:,h]) @ J[h]   (M=1024, K=64, N=64 per pair)
// grid: (B*H, S/64), 256 threads, 4x4 microtile.
// ---------------------------------------------------------------------------
__global__ void __launch_bounds__(256) tqj_kernel(
    const float* __restrict__ Q, const float* __restrict__ J,
    float* __restrict__ Out)
{
    __shared__ __align__(16) float As[64][64];   // [k][row] (tanh applied)
    __shared__ __align__(16) float Js[64][64];   // [k][n]
    int tid = threadIdx.x;
    int bh = blockIdx.x; int b = bh >> 4, h = bh & 15;
    int s0 = blockIdx.y << 6;

    #pragma unroll
    for (int i = 0; i < 4; i++) {
        int idx = tid + (i << 8);                // float4 index 0..1023
        int r = idx >> 4, kq = (idx & 15) << 2;
        float4 v = *(const float4*)&Q[((size_t)(b * SS + s0 + r)) * DD + h * HD + kq];
        As[kq + 0][r] = tanhf(v.x); As[kq + 1][r] = tanhf(v.y);
        As[kq + 2][r] = tanhf(v.z); As[kq + 3][r] = tanhf(v.w);
        ((float4*)Js)[idx] = *(const float4*)&J[(size_t)h * HD * HD + idx * 4];
    }
    __syncthreads();

    int tx = tid & 15, ty = tid >> 4;
    float c[4][4] = {};
    #pragma unroll 8
    for (int kk = 0; kk < 64; kk++) {
        float a[4], bv[4];
        *(float4*)a  = *(const float4*)&As[kk][ty * 4];
        *(float4*)bv = *(const float4*)&Js[kk][tx * 4];
        #pragma unroll
        for (int i = 0; i < 4; i++)
            #pragma unroll
            for (int j = 0; j < 4; j++)
                c[i][j] = fmaf(a[i], bv[j], c[i][j]);
    }
    #pragma unroll
    for (int i = 0; i < 4; i++) {
        float4 v; v.x = c[i][0]; v.y = c[i][1]; v.z = c[i][2]; v.w = c[i][3];
        *(float4*)&Out[((size_t)(b * SS + s0 + ty * 4 + i)) * DD + h * HD + tx * 4] = v;
    }
}

// ---------------------------------------------------------------------------
// Flash attention with tanh-Hopfield score correction.
// score = QK/8 + lam * (tQJ . tanhK);  online softmax;  O = P V.
// grid (S/64, B*H), 64 threads (one query per thread).
// q / tQJ rows register-resident; K / tanhK / V staged in dynamic shared.
// ---------------------------------------------------------------------------
#define ATT_PAD 68
#define ATT_SMEM (3 * 64 * ATT_PAD * 4)

__global__ void __launch_bounds__(64) attn_kernel(
    const float* __restrict__ Q,  const float* __restrict__ K,
    const float* __restrict__ TK, const float* __restrict__ V,
    const float* __restrict__ TQJ, float* __restrict__ O,
    const float* __restrict__ lam_p)
{
    extern __shared__ float sm[];
    float* Ks  = sm;
    float* TKs = Ks  + 64 * ATT_PAD;
    float* Vs  = TKs + 64 * ATT_PAD;

    int tid = threadIdx.x;
    int bh = blockIdx.y; int b = bh >> 4, h = bh & 15;
    int q0 = blockIdx.x << 6;
    const float lam = __ldg(lam_p);

    // Own query row into registers
    float4 q[16], t[16];
    {
        size_t qrow = ((size_t)(b * SS + q0 + tid)) * DD + h * HD;
        #pragma unroll
        for (int d = 0; d < 16; d++) {
            q[d] = *(const float4*)&Q[qrow + 4 * d];
            t[d] = *(const float4*)&TQJ[qrow + 4 * d];
        }
    }

    float o[64];
    #pragma unroll
    for (int d = 0; d < 64; d++) o[d] = 0.f;
    float m = -1e30f, l = 0.f;

    for (int k0 = 0; k0 < SS; k0 += 64) {
        __syncthreads();
        #pragma unroll
        for (int i = 0; i < 16; i++) {
            int idx = tid + (i << 6);
            int r = idx >> 4, dq = (idx & 15) << 2;
            size_t ga = ((size_t)(b * SS + k0 + r)) * DD + h * HD + dq;
            *(float4*)&Ks [r * ATT_PAD + dq] = *(const float4*)&K [ga];
            *(float4*)&TKs[r * ATT_PAD + dq] = *(const float4*)&TK[ga];
            *(float4*)&Vs [r * ATT_PAD + dq] = *(const float4*)&V [ga];
        }
        __syncthreads();

        #pragma unroll 2
        for (int j = 0; j < 64; j++) {
            const float4* k4  = (const float4*)&Ks [j * ATT_PAD];
            const float4* tk4 = (const float4*)&TKs[j * ATT_PAD];
            float acc = 0.f, accd = 0.f;
            #pragma unroll
            for (int d = 0; d < 16; d++) {
                float4 a = q[d], c = k4[d];
                acc = fmaf(a.x, c.x, acc); acc = fmaf(a.y, c.y, acc);
                acc = fmaf(a.z, c.z, acc); acc = fmaf(a.w, c.w, acc);
                float4 e = t[d], f = tk4[d];
                accd = fmaf(e.x, f.x, accd); accd = fmaf(e.y, f.y, accd);
                accd = fmaf(e.z, f.z, accd); accd = fmaf(e.w, f.w, accd);
            }
            float sj = fmaf(lam, accd, acc * INV_SCALE);
            if (sj > m) {
                float corr = __expf(m - sj);
                l *= corr;
                #pragma unroll
                for (int d = 0; d < 64; d++) o[d] *= corr;
                m = sj;
            }
            float p = __expf(sj - m);
            l += p;
            const float4* v4 = (const float4*)&Vs[j * ATT_PAD];
            #pragma unroll
            for (int d = 0; d < 16; d++) {
                float4 v = v4[d];
                o[4 * d + 0] = fmaf(p, v.x, o[4 * d + 0]);
                o[4 * d + 1] = fmaf(p, v.y, o[4 * d + 1]);
                o[4 * d + 2] = fmaf(p, v.z, o[4 * d + 2]);
                o[4 * d + 3] = fmaf(p, v.w, o[4 * d + 3]);
            }
        }
    }

    float inv = 1.f / l;
    size_t ob = ((size_t)(b * SS + q0 + tid)) * DD + h * HD;
    #pragma unroll
    for (int d = 0; d < 16; d++) {
        float4 v;
        v.x = o[4 * d + 0] * inv; v.y = o[4 * d + 1] * inv;
        v.z = o[4 * d + 2] * inv; v.w = o[4 * d + 3] * inv;
        *(float4*)&O[ob + 4 * d] = v;
    }
}

// ---------------------------------------------------------------------------
// Host driver
// ---------------------------------------------------------------------------
static float* symaddr(const void* s)
{
    void* p = nullptr;
    cudaGetSymbolAddress(&p, s);
    return (float*)p;
}

extern "C" void kernel_launch(void* const* d_in, const int* in_sizes, int n_in,
                              void* d_out, int out_size)
{
    (void)in_sizes; (void)n_in; (void)out_size;

    const float* x    = (const float*)d_in[0];
    const float* wq   = (const float*)d_in[1];
    const float* bq   = (const float*)d_in[2];
    const float* wk   = (const float*)d_in[3];
    const float* bk   = (const float*)d_in[4];
    const float* wv   = (const float*)d_in[5];
    const float* bv   = (const float*)d_in[6];
    const float* wo   = (const float*)d_in[7];
    const float* bo   = (const float*)d_in[8];
    const float* Jat  = (const float*)d_in[9];
    const float* lam  = (const float*)d_in[10];
    const float* gat  = (const float*)d_in[11];
    const float* bat  = (const float*)d_in[12];
    const float* W1   = (const float*)d_in[13];
    const float* b1   = (const float*)d_in[14];
    const float* J1   = (const float*)d_in[15];
    const float* g1   = (const float*)d_in[17];
    const float* be1  = (const float*)d_in[18];
    const float* W2   = (const float*)d_in[19];
    const float* b2   = (const float*)d_in[20];
    const float* J2   = (const float*)d_in[21];
    const float* g2   = (const float*)d_in[23];
    const float* be2  = (const float*)d_in[24];
    const float* gf   = (const float*)d_in[25];
    const float* bf   = (const float*)d_in[26];
    float* out = (float*)d_out;

    float* p_xn   = symaddr(buf_xn);
    float* p_Q    = symaddr(buf_Q);
    float* p_K    = symaddr(buf_K);
    float* p_tK   = symaddr(buf_tK);
    float* p_V    = symaddr(buf_V);
    float* p_tQJ  = symaddr(buf_tQJ);
    float* p_ao   = symaddr(buf_ao);
    float* p_x1   = symaddr(buf_x1);
    float* p_th   = symaddr(buf_th);
    float* p_hhat = symaddr(buf_hhat);
    float* p_h1   = symaddr(buf_h1);
    float* p_th1  = symaddr(buf_th1);

    cudaFuncSetAttribute(attn_kernel,
                         cudaFuncAttributeMaxDynamicSharedMemorySize, ATT_SMEM);

    // --- attention branch -------------------------------------------------
    ln_kernel<<<NT, 256>>>(x, gat, bat, p_xn, nullptr, DD);

    dim3 gProj(DD / 64, NT / 128);
    gemm_kernel<false, false><<<gProj, 256>>>(p_xn, wq, bq, nullptr, p_Q, nullptr, NT, DD, DD);
    gemm_kernel<false, true ><<<gProj, 256>>>(p_xn, wk, bk, nullptr, p_K, p_tK,   NT, DD, DD);
    gemm_kernel<false, false><<<gProj, 256>>>(p_xn, wv, bv, nullptr, p_V, nullptr, NT, DD, DD);

    tqj_kernel<<<dim3(BB * HH, SS / 64), 256>>>(p_Q, Jat, p_tQJ);

    attn_kernel<<<dim3(SS / 64, BB * HH), 64, ATT_SMEM>>>(
        p_Q, p_K, p_tK, p_V, p_tQJ, p_ao, lam);

    gemm_kernel<true, false><<<gProj, 256>>>(p_ao, wo, bo, x, p_x1, nullptr, NT, DD, DD);

    // --- QBNN FFN ---------------------------------------------------------
    ln_kernel<<<NT, 256>>>(p_x1, gf, bf, p_xn, p_th, DD);

    qbnn_gemm_kernel<<<dim3(FFD / 64, NT / 128), 256>>>(
        p_xn, p_th, W1, J1, b1, p_hhat, NT, FFD, DD);

    ln_gelu_kernel<<<NT, 256>>>(p_hhat, g1, be1, nullptr, p_h1, p_th1, FFD);

    qbnn_gemm_kernel<<<dim3(DD / 64, NT / 128), 256>>>(
        p_h1, p_th1, W2, J2, b2, p_hhat, NT, DD, FFD);

    ln_gelu_kernel<<<NT, 256>>>(p_hhat, g2, be2, p_x1, out, nullptr, DD);
}

// round 2
// speedup vs baseline: 1.7677x; 1.7677x over previous
#include <cuda_runtime.h>
#include <cuda_bf16.h>
#include <math.h>
#include <stdint.h>

// ---------------------------------------------------------------------------
// Problem constants
// ---------------------------------------------------------------------------
#define BB   4
#define SS   1024
#define DD   1024
#define HH   16
#define HD   64
#define FFD  4096
#define NT   (BB*SS)          // 4096 tokens
#define INV_SCALE 0.125f      // 1/sqrt(64)
#define LAM_EFF   0.5f        // LAMBDA_MIN + (MAX-MIN)*... == 0.5 exactly

// ---------------------------------------------------------------------------
// Scratch (device globals; no runtime allocation allowed)
// ---------------------------------------------------------------------------
__device__ float buf_xn  [NT*DD];     // LN output
__device__ float buf_Q   [NT*DD];
__device__ float buf_K   [NT*DD];
__device__ float buf_tK  [NT*DD];     // tanh(K)
__device__ float buf_V   [NT*DD];
__device__ float buf_tQJ [NT*DD];     // tanh(Q) @ J  per head
__device__ float buf_ao  [NT*DD];     // attention output (pre out-proj)
__device__ float buf_x1  [NT*DD];     // x + attn (residual stream)
__device__ float buf_th  [NT*DD];     // tanh(LN_ffn(x1))
__device__ float buf_hhat[NT*FFD];    // h_tilde scratch
__device__ float buf_dlt [NT*FFD];    // delta scratch
__device__ float buf_h1  [NT*FFD];    // gelu(LN(hhat1))
__device__ float buf_th1 [NT*FFD];    // tanh(h1)

// ---------------------------------------------------------------------------
// TF32 helpers
// ---------------------------------------------------------------------------
__device__ __forceinline__ uint32_t f2tf(float f)
{
    uint32_t u;
    asm("cvt.rna.tf32.f32 %0, %1;" : "=r"(u) : "f"(f));
    return u;
}

__device__ __forceinline__ void mma8(float* c,
    uint32_t a0, uint32_t a1, uint32_t a2, uint32_t a3,
    uint32_t b0, uint32_t b1)
{
    asm volatile(
        "mma.sync.aligned.m16n8k8.row.col.f32.tf32.tf32.f32 "
        "{%0,%1,%2,%3},{%4,%5,%6,%7},{%8,%9},{%0,%1,%2,%3};"
        : "+f"(c[0]), "+f"(c[1]), "+f"(c[2]), "+f"(c[3])
        : "r"(a0), "r"(a1), "r"(a2), "r"(a3), "r"(b0), "r"(b1));
}

// ---------------------------------------------------------------------------
// TF32 tensor-core GEMM: C = A[M,K] @ B[K,N] (+bias) (+Res), opt tanh output.
// Block 128x64, BK=32, 8 warps (4x2) of 32x32 warp tiles (2x4 m16n8k8 mmas).
// ---------------------------------------------------------------------------
#define BM 128
#define BN 64
#define BK 32
#define ASTR (BK+4)   // 36: conflict-free A fragment loads
#define BSTR (BN+8)   // 72: conflict-free B fragment loads

template<bool BIAS, bool RES, bool TOUT>
__global__ void __launch_bounds__(256) gemm_tf32_kernel(
    const float* __restrict__ A, const float* __restrict__ Bm,
    const float* __restrict__ bias, const float* __restrict__ Res,
    float* __restrict__ C, float* __restrict__ CT,
    int M, int N, int K)
{
    __shared__ uint32_t As[BM][ASTR];
    __shared__ uint32_t Bs[BK][BSTR];

    int tid = threadIdx.x;
    int bn = blockIdx.x * BN, bm = blockIdx.y * BM;
    int wid = tid >> 5, lane = tid & 31;
    int wm = wid & 3, wn = wid >> 2;       // 4 warps along M, 2 along N
    int gid = lane >> 2, tig = lane & 3;

    float c[2][4][4] = {};

    for (int k0 = 0; k0 < K; k0 += BK) {
        #pragma unroll
        for (int i = 0; i < 4; i++) {
            int idx = tid + (i << 8);
            int r = idx >> 3, cq = (idx & 7) << 2;
            float4 v = *(const float4*)&A[(size_t)(bm + r) * K + k0 + cq];
            As[r][cq + 0] = f2tf(v.x); As[r][cq + 1] = f2tf(v.y);
            As[r][cq + 2] = f2tf(v.z); As[r][cq + 3] = f2tf(v.w);
        }
        #pragma unroll
        for (int i = 0; i < 2; i++) {
            int idx = tid + (i << 8);
            int r = idx >> 4, cq = (idx & 15) << 2;
            float4 v = *(const float4*)&Bm[(size_t)(k0 + r) * N + bn + cq];
            Bs[r][cq + 0] = f2tf(v.x); Bs[r][cq + 1] = f2tf(v.y);
            Bs[r][cq + 2] = f2tf(v.z); Bs[r][cq + 3] = f2tf(v.w);
        }
        __syncthreads();

        #pragma unroll
        for (int kk = 0; kk < 4; kk++) {
            int kb = kk << 3;
            uint32_t a[2][4], b[4][2];
            #pragma unroll
            for (int mt = 0; mt < 2; mt++) {
                int ar = wm * 32 + mt * 16 + gid;
                a[mt][0] = As[ar    ][kb + tig];
                a[mt][1] = As[ar + 8][kb + tig];
                a[mt][2] = As[ar    ][kb + tig + 4];
                a[mt][3] = As[ar + 8][kb + tig + 4];
            }
            #pragma unroll
            for (int nt = 0; nt < 4; nt++) {
                int bc = wn * 32 + nt * 8 + gid;
                b[nt][0] = Bs[kb + tig    ][bc];
                b[nt][1] = Bs[kb + tig + 4][bc];
            }
            #pragma unroll
            for (int mt = 0; mt < 2; mt++)
                #pragma unroll
                for (int nt = 0; nt < 4; nt++)
                    mma8(c[mt][nt], a[mt][0], a[mt][1], a[mt][2], a[mt][3],
                         b[nt][0], b[nt][1]);
        }
        __syncthreads();
    }

    #pragma unroll
    for (int mt = 0; mt < 2; mt++) {
        #pragma unroll
        for (int nt = 0; nt < 4; nt++) {
            int col = bn + wn * 32 + nt * 8 + tig * 2;
            float2 bi = make_float2(0.f, 0.f);
            if (BIAS) bi = *(const float2*)&bias[col];
            #pragma unroll
            for (int half = 0; half < 2; half++) {
                int row = bm + wm * 32 + mt * 16 + gid + half * 8;
                float2 v;
                v.x = c[mt][nt][half * 2 + 0] + bi.x;
                v.y = c[mt][nt][half * 2 + 1] + bi.y;
                if (RES) {
                    float2 r = *(const float2*)&Res[(size_t)row * N + col];
                    v.x += r.x; v.y += r.y;
                }
                *(float2*)&C[(size_t)row * N + col] = v;
                if (TOUT) {
                    float2 t; t.x = tanhf(v.x); t.y = tanhf(v.y);
                    *(float2*)&CT[(size_t)row * N + col] = t;
                }
            }
        }
    }
}

// ---------------------------------------------------------------------------
// LayerNorm: one block per row; optional tanh side-output
// ---------------------------------------------------------------------------
__global__ void __launch_bounds__(256) ln_kernel(
    const float* __restrict__ X, const float* __restrict__ g,
    const float* __restrict__ b, float* __restrict__ Y,
    float* __restrict__ YT, int N)
{
    int row = blockIdx.x;
    const float* x = X + (size_t)row * N;
    float s = 0.f, s2 = 0.f;
    for (int i = threadIdx.x; i < N; i += 256) {
        float v = x[i];
        s += v; s2 = fmaf(v, v, s2);
    }
    __shared__ float sh[64];
    for (int o = 16; o > 0; o >>= 1) {
        s  += __shfl_down_sync(0xffffffffu, s,  o);
        s2 += __shfl_down_sync(0xffffffffu, s2, o);
    }
    int wid = threadIdx.x >> 5, lane = threadIdx.x & 31;
    if (lane == 0) { sh[wid] = s; sh[wid + 32] = s2; }
    __syncthreads();
    if (threadIdx.x == 0) {
        float ts = 0.f, ts2 = 0.f;
        for (int w = 0; w < 8; w++) { ts += sh[w]; ts2 += sh[w + 32]; }
        float mu  = ts / N;
        float var = ts2 / N - mu * mu;
        sh[0] = mu; sh[1] = rsqrtf(var + 1e-5f);
    }
    __syncthreads();
    float mu = sh[0], rstd = sh[1];
    for (int i = threadIdx.x; i < N; i += 256) {
        float v = (x[i] - mu) * rstd * g[i] + b[i];
        Y[(size_t)row * N + i] = v;
        if (YT) YT[(size_t)row * N + i] = tanhf(v);
    }
}

// ---------------------------------------------------------------------------
// QBNN combine + LayerNorm + exact GELU (+ optional residual, tanh output).
// v = ht + 0.5*delta*tanh(ht); y = gelu(LN(v)) (+Res); YT = tanh(y).
// Row staged in dynamic shared so the combine runs once.
// ---------------------------------------------------------------------------
__global__ void __launch_bounds__(256) qln_gelu_kernel(
    const float* __restrict__ HT, const float* __restrict__ DLT,
    const float* __restrict__ g,  const float* __restrict__ b,
    const float* __restrict__ Res, float* __restrict__ Y,
    float* __restrict__ YT, int N)
{
    extern __shared__ float rowbuf[];
    __shared__ float sh[64];
    int row = blockIdx.x;
    size_t base = (size_t)row * N;

    float s = 0.f, s2 = 0.f;
    for (int i = threadIdx.x; i < N; i += 256) {
        float ht = HT[base + i];
        float v  = fmaf(LAM_EFF * DLT[base + i], tanhf(ht), ht);
        rowbuf[i] = v;
        s += v; s2 = fmaf(v, v, s2);
    }
    for (int o = 16; o > 0; o >>= 1) {
        s  += __shfl_down_sync(0xffffffffu, s,  o);
        s2 += __shfl_down_sync(0xffffffffu, s2, o);
    }
    int wid = threadIdx.x >> 5, lane = threadIdx.x & 31;
    if (lane == 0) { sh[wid] = s; sh[wid + 32] = s2; }
    __syncthreads();
    if (threadIdx.x == 0) {
        float ts = 0.f, ts2 = 0.f;
        for (int w = 0; w < 8; w++) { ts += sh[w]; ts2 += sh[w + 32]; }
        float mu  = ts / N;
        float var = ts2 / N - mu * mu;
        sh[0] = mu; sh[1] = rsqrtf(var + 1e-5f);
    }
    __syncthreads();
    float mu = sh[0], rstd = sh[1];
    for (int i = threadIdx.x; i < N; i += 256) {
        float v  = (rowbuf[i] - mu) * rstd * g[i] + b[i];
        float ge = v * normcdff(v);
        float o  = Res ? Res[base + i] + ge : ge;
        Y[base + i] = o;
        if (YT) YT[base + i] = tanhf(o);
    }
}

// ---------------------------------------------------------------------------
// tQJ: per (b,h): tanh(Q[b,:,h]) @ J[h]
// ---------------------------------------------------------------------------
__global__ void __launch_bounds__(256) tqj_kernel(
    const float* __restrict__ Q, const float* __restrict__ J,
    float* __restrict__ Out)
{
    __shared__ __align__(16) float As[64][64];
    __shared__ __align__(16) float Js[64][64];
    int tid = threadIdx.x;
    int bh = blockIdx.x; int b = bh >> 4, h = bh & 15;
    int s0 = blockIdx.y << 6;

    #pragma unroll
    for (int i = 0; i < 4; i++) {
        int idx = tid + (i << 8);
        int r = idx >> 4, kq = (idx & 15) << 2;
        float4 v = *(const float4*)&Q[((size_t)(b * SS + s0 + r)) * DD + h * HD + kq];
        As[kq + 0][r] = tanhf(v.x); As[kq + 1][r] = tanhf(v.y);
        As[kq + 2][r] = tanhf(v.z); As[kq + 3][r] = tanhf(v.w);
        ((float4*)Js)[idx] = *(const float4*)&J[(size_t)h * HD * HD + idx * 4];
    }
    __syncthreads();

    int tx = tid & 15, ty = tid >> 4;
    float c[4][4] = {};
    #pragma unroll 8
    for (int kk = 0; kk < 64; kk++) {
        float a[4], bv[4];
        *(float4*)a  = *(const float4*)&As[kk][ty * 4];
        *(float4*)bv = *(const float4*)&Js[kk][tx * 4];
        #pragma unroll
        for (int i = 0; i < 4; i++)
            #pragma unroll
            for (int j = 0; j < 4; j++)
                c[i][j] = fmaf(a[i], bv[j], c[i][j]);
    }
    #pragma unroll
    for (int i = 0; i < 4; i++) {
        float4 v; v.x = c[i][0]; v.y = c[i][1]; v.z = c[i][2]; v.w = c[i][3];
        *(float4*)&Out[((size_t)(b * SS + s0 + ty * 4 + i)) * DD + h * HD + tx * 4] = v;
    }
}

// ---------------------------------------------------------------------------
// Flash attention with tanh-Hopfield score correction.
// ---------------------------------------------------------------------------
#define ATT_PAD 68
#define ATT_SMEM (3 * 64 * ATT_PAD * 4)

__global__ void __launch_bounds__(64) attn_kernel(
    const float* __restrict__ Q,  const float* __restrict__ K,
    const float* __restrict__ TK, const float* __restrict__ V,
    const float* __restrict__ TQJ, float* __restrict__ O,
    const float* __restrict__ lam_p)
{
    extern __shared__ float sm[];
    float* Ks  = sm;
    float* TKs = Ks  + 64 * ATT_PAD;
    float* Vs  = TKs + 64 * ATT_PAD;

    int tid = threadIdx.x;
    int bh = blockIdx.y; int b = bh >> 4, h = bh & 15;
    int q0 = blockIdx.x << 6;
    const float lam = __ldg(lam_p);

    float4 q[16], t[16];
    {
        size_t qrow = ((size_t)(b * SS + q0 + tid)) * DD + h * HD;
        #pragma unroll
        for (int d = 0; d < 16; d++) {
            q[d] = *(const float4*)&Q[qrow + 4 * d];
            t[d] = *(const float4*)&TQJ[qrow + 4 * d];
        }
    }

    float o[64];
    #pragma unroll
    for (int d = 0; d < 64; d++) o[d] = 0.f;
    float m = -1e30f, l = 0.f;

    for (int k0 = 0; k0 < SS; k0 += 64) {
        __syncthreads();
        #pragma unroll
        for (int i = 0; i < 16; i++) {
            int idx = tid + (i << 6);
            int r = idx >> 4, dq = (idx & 15) << 2;
            size_t ga = ((size_t)(b * SS + k0 + r)) * DD + h * HD + dq;
            *(float4*)&Ks [r * ATT_PAD + dq] = *(const float4*)&K [ga];
            *(float4*)&TKs[r * ATT_PAD + dq] = *(const float4*)&TK[ga];
            *(float4*)&Vs [r * ATT_PAD + dq] = *(const float4*)&V [ga];
        }
        __syncthreads();

        #pragma unroll 2
        for (int j = 0; j < 64; j++) {
            const float4* k4  = (const float4*)&Ks [j * ATT_PAD];
            const float4* tk4 = (const float4*)&TKs[j * ATT_PAD];
            float acc = 0.f, accd = 0.f;
            #pragma unroll
            for (int d = 0; d < 16; d++) {
                float4 a = q[d], c = k4[d];
                acc = fmaf(a.x, c.x, acc); acc = fmaf(a.y, c.y, acc);
                acc = fmaf(a.z, c.z, acc); acc = fmaf(a.w, c.w, acc);
                float4 e = t[d], f = tk4[d];
                accd = fmaf(e.x, f.x, accd); accd = fmaf(e.y, f.y, accd);
                accd = fmaf(e.z, f.z, accd); accd = fmaf(e.w, f.w, accd);
            }
            float sj = fmaf(lam, accd, acc * INV_SCALE);
            if (sj > m) {
                float corr = __expf(m - sj);
                l *= corr;
                #pragma unroll
                for (int d = 0; d < 64; d++) o[d] *= corr;
                m = sj;
            }
            float p = __expf(sj - m);
            l += p;
            const float4* v4 = (const float4*)&Vs[j * ATT_PAD];
            #pragma unroll
            for (int d = 0; d < 16; d++) {
                float4 v = v4[d];
                o[4 * d + 0] = fmaf(p, v.x, o[4 * d + 0]);
                o[4 * d + 1] = fmaf(p, v.y, o[4 * d + 1]);
                o[4 * d + 2] = fmaf(p, v.z, o[4 * d + 2]);
                o[4 * d + 3] = fmaf(p, v.w, o[4 * d + 3]);
            }
        }
    }

    float inv = 1.f / l;
    size_t ob = ((size_t)(b * SS + q0 + tid)) * DD + h * HD;
    #pragma unroll
    for (int d = 0; d < 16; d++) {
        float4 v;
        v.x = o[4 * d + 0] * inv; v.y = o[4 * d + 1] * inv;
        v.z = o[4 * d + 2] * inv; v.w = o[4 * d + 3] * inv;
        *(float4*)&O[ob + 4 * d] = v;
    }
}

// ---------------------------------------------------------------------------
// Host driver
// ---------------------------------------------------------------------------
static float* symaddr(const void* s)
{
    void* p = nullptr;
    cudaGetSymbolAddress(&p, s);
    return (float*)p;
}

extern "C" void kernel_launch(void* const* d_in, const int* in_sizes, int n_in,
                              void* d_out, int out_size)
{
    (void)in_sizes; (void)n_in; (void)out_size;

    const float* x    = (const float*)d_in[0];
    const float* wq   = (const float*)d_in[1];
    const float* bq   = (const float*)d_in[2];
    const float* wk   = (const float*)d_in[3];
    const float* bk   = (const float*)d_in[4];
    const float* wv   = (const float*)d_in[5];
    const float* bv   = (const float*)d_in[6];
    const float* wo   = (const float*)d_in[7];
    const float* bo   = (const float*)d_in[8];
    const float* Jat  = (const float*)d_in[9];
    const float* lam  = (const float*)d_in[10];
    const float* gat  = (const float*)d_in[11];
    const float* bat  = (const float*)d_in[12];
    const float* W1   = (const float*)d_in[13];
    const float* b1   = (const float*)d_in[14];
    const float* J1   = (const float*)d_in[15];
    const float* g1   = (const float*)d_in[17];
    const float* be1  = (const float*)d_in[18];
    const float* W2   = (const float*)d_in[19];
    const float* b2   = (const float*)d_in[20];
    const float* J2   = (const float*)d_in[21];
    const float* g2   = (const float*)d_in[23];
    const float* be2  = (const float*)d_in[24];
    const float* gf   = (const float*)d_in[25];
    const float* bf   = (const float*)d_in[26];
    float* out = (float*)d_out;

    float* p_xn   = symaddr(buf_xn);
    float* p_Q    = symaddr(buf_Q);
    float* p_K    = symaddr(buf_K);
    float* p_tK   = symaddr(buf_tK);
    float* p_V    = symaddr(buf_V);
    float* p_tQJ  = symaddr(buf_tQJ);
    float* p_ao   = symaddr(buf_ao);
    float* p_x1   = symaddr(buf_x1);
    float* p_th   = symaddr(buf_th);
    float* p_hhat = symaddr(buf_hhat);
    float* p_dlt  = symaddr(buf_dlt);
    float* p_h1   = symaddr(buf_h1);
    float* p_th1  = symaddr(buf_th1);

    cudaFuncSetAttribute(attn_kernel,
                         cudaFuncAttributeMaxDynamicSharedMemorySize, ATT_SMEM);

    // --- attention branch -------------------------------------------------
    ln_kernel<<<NT, 256>>>(x, gat, bat, p_xn, nullptr, DD);

    dim3 gProj(DD / BN, NT / BM);
    gemm_tf32_kernel<true, false, false><<<gProj, 256>>>(
        p_xn, wq, bq, nullptr, p_Q, nullptr, NT, DD, DD);
    gemm_tf32_kernel<true, false, true ><<<gProj, 256>>>(
        p_xn, wk, bk, nullptr, p_K, p_tK, NT, DD, DD);
    gemm_tf32_kernel<true, false, false><<<gProj, 256>>>(
        p_xn, wv, bv, nullptr, p_V, nullptr, NT, DD, DD);

    tqj_kernel<<<dim3(BB * HH, SS / 64), 256>>>(p_Q, Jat, p_tQJ);

    attn_kernel<<<dim3(SS / 64, BB * HH), 64, ATT_SMEM>>>(
        p_Q, p_K, p_tK, p_V, p_tQJ, p_ao, lam);

    gemm_tf32_kernel<true, true, false><<<gProj, 256>>>(
        p_ao, wo, bo, x, p_x1, nullptr, NT, DD, DD);

    // --- QBNN FFN layer 1 -------------------------------------------------
    ln_kernel<<<NT, 256>>>(p_x1, gf, bf, p_xn, p_th, DD);

    dim3 gF1(FFD / BN, NT / BM);
    gemm_tf32_kernel<true,  false, false><<<gF1, 256>>>(
        p_xn, W1, b1, nullptr, p_hhat, nullptr, NT, FFD, DD);
    gemm_tf32_kernel<false, false, false><<<gF1, 256>>>(
        p_th, J1, nullptr, nullptr, p_dlt, nullptr, NT, FFD, DD);

    qln_gelu_kernel<<<NT, 256, FFD * sizeof(float)>>>(
        p_hhat, p_dlt, g1, be1, nullptr, p_h1, p_th1, FFD);

    // --- QBNN FFN layer 2 -------------------------------------------------
    dim3 gF2(DD / BN, NT / BM);
    gemm_tf32_kernel<true,  false, false><<<gF2, 256>>>(
        p_h1, W2, b2, nullptr, p_hhat, nullptr, NT, DD, FFD);
    gemm_tf32_kernel<false, false, false><<<gF2, 256>>>(
        p_th1, J2, nullptr, nullptr, p_dlt, nullptr, NT, DD, FFD);

    qln_gelu_kernel<<<NT, 256, DD * sizeof(float)>>>(
        p_hhat, p_dlt, g2, be2, p_x1, out, nullptr, DD);
}

// round 3
// speedup vs baseline: 2.3446x; 1.3264x over previous
#include <cuda_runtime.h>
#include <cuda_bf16.h>
#include <math.h>
#include <stdint.h>

// ---------------------------------------------------------------------------
// Problem constants
// ---------------------------------------------------------------------------
#define BB   4
#define SS   1024
#define DD   1024
#define HH   16
#define HD   64
#define FFD  4096
#define NT   (BB*SS)          // 4096 tokens
#define INV_SCALE 0.125f      // 1/sqrt(64)
#define LAM_EFF   0.5f

// ---------------------------------------------------------------------------
// Scratch (device globals)
// ---------------------------------------------------------------------------
__device__ float buf_xn  [NT*DD];
__device__ float buf_Q   [NT*DD];
__device__ float buf_K   [NT*DD];
__device__ float buf_tK  [NT*DD];
__device__ float buf_V   [NT*DD];
__device__ float buf_tQJ [NT*DD];
__device__ float buf_ao  [NT*DD];
__device__ float buf_x1  [NT*DD];
__device__ float buf_th  [NT*DD];
__device__ float buf_hhat[NT*FFD];
__device__ float buf_dlt [NT*FFD];
__device__ float buf_h1  [NT*FFD];
__device__ float buf_th1 [NT*FFD];

// ---------------------------------------------------------------------------
// Async-copy helpers
// ---------------------------------------------------------------------------
__device__ __forceinline__ void cp16(uint32_t smem_dst, const void* gsrc)
{
    asm volatile("cp.async.cg.shared.global [%0], [%1], 16;\n"
                 :: "r"(smem_dst), "l"(gsrc));
}
__device__ __forceinline__ void cp_commit()
{
    asm volatile("cp.async.commit_group;\n");
}
template<int N> __device__ __forceinline__ void cp_wait()
{
    asm volatile("cp.async.wait_group %0;\n" :: "n"(N));
}

__device__ __forceinline__ void mma8(float* c,
    uint32_t a0, uint32_t a1, uint32_t a2, uint32_t a3,
    uint32_t b0, uint32_t b1)
{
    asm volatile(
        "mma.sync.aligned.m16n8k8.row.col.f32.tf32.tf32.f32 "
        "{%0,%1,%2,%3},{%4,%5,%6,%7},{%8,%9},{%0,%1,%2,%3};"
        : "+f"(c[0]), "+f"(c[1]), "+f"(c[2]), "+f"(c[3])
        : "r"(a0), "r"(a1), "r"(a2), "r"(a3), "r"(b0), "r"(b1));
}

// ---------------------------------------------------------------------------
// TF32 GEMM v2: C = A[M,K] @ B[K,N] (+bias) (+Res), optional tanh output.
// Block 128x128, BK=32, 2-stage cp.async pipeline, 8 warps (2 M x 4 N),
// warp tile 64x32 (4x4 m16n8k8). Raw fp32 bits fed as tf32 (HW truncation).
// ---------------------------------------------------------------------------
#define BM 128
#define BN 128
#define BK 32
#define ASTR 36                 // floats per A row  (bank: 4r+c, conflict-free)
#define BSTR 136                // floats per B row  (bank: 8r+c, conflict-free)
#define ASZ (BM*ASTR)           // 4608 floats per stage
#define BSZ (BK*BSTR)           // 4352 floats per stage
#define GEMM_SMEM ((2*ASZ + 2*BSZ) * 4)   // 71680 bytes

template<bool BIAS, bool RES, bool TOUT>
__global__ void __launch_bounds__(256) gemm_tf32_kernel(
    const float* __restrict__ A, const float* __restrict__ Bm,
    const float* __restrict__ bias, const float* __restrict__ Res,
    float* __restrict__ C, float* __restrict__ CT,
    int M, int N, int K)
{
    extern __shared__ float smem[];
    float* As = smem;                 // 2 stages
    float* Bs = smem + 2 * ASZ;       // 2 stages
    const uint32_t smem_u = (uint32_t)__cvta_generic_to_shared(smem);
    const uint32_t As_u = smem_u;
    const uint32_t Bs_u = smem_u + 2 * ASZ * 4;

    const int tid = threadIdx.x;
    const int bn = blockIdx.x * BN, bm = blockIdx.y * BM;
    const int wid = tid >> 5, lane = tid & 31;
    const int wm = wid & 1, wn = wid >> 1;        // 2 warps M, 4 warps N
    const int gid = lane >> 2, tig = lane & 3;

    float c[4][4][4] = {};

    // ---- stage loaders (cp.async) ----
    auto load_stage = [&](int k0, int st) {
        uint32_t a_base = As_u + st * ASZ * 4;
        uint32_t b_base = Bs_u + st * BSZ * 4;
        #pragma unroll
        for (int i = 0; i < 4; i++) {
            int idx = tid + (i << 8);
            int r = idx >> 3, cq = (idx & 7) << 2;
            cp16(a_base + (r * ASTR + cq) * 4,
                 &A[(size_t)(bm + r) * K + k0 + cq]);
        }
        #pragma unroll
        for (int i = 0; i < 4; i++) {
            int idx = tid + (i << 8);
            int r = idx >> 5, cq = (idx & 31) << 2;
            cp16(b_base + (r * BSTR + cq) * 4,
                 &Bm[(size_t)(k0 + r) * N + bn + cq]);
        }
        cp_commit();
    };

    load_stage(0, 0);
    const int KT = K / BK;

    for (int kt = 0; kt < KT; kt++) {
        if (kt + 1 < KT) {
            load_stage((kt + 1) * BK, (kt + 1) & 1);
            cp_wait<1>();
        } else {
            cp_wait<0>();
        }
        __syncthreads();

        const uint32_t* Au = (const uint32_t*)(As + (kt & 1) * ASZ);
        const uint32_t* Bu = (const uint32_t*)(Bs + (kt & 1) * BSZ);

        #pragma unroll
        for (int kk = 0; kk < 4; kk++) {
            int kb = kk << 3;
            uint32_t a[4][4], b[4][2];
            #pragma unroll
            for (int mt = 0; mt < 4; mt++) {
                int ar = wm * 64 + mt * 16 + gid;
                a[mt][0] = Au[(ar    ) * ASTR + kb + tig];
                a[mt][1] = Au[(ar + 8) * ASTR + kb + tig];
                a[mt][2] = Au[(ar    ) * ASTR + kb + tig + 4];
                a[mt][3] = Au[(ar + 8) * ASTR + kb + tig + 4];
            }
            #pragma unroll
            for (int nt = 0; nt < 4; nt++) {
                int bc = wn * 32 + nt * 8 + gid;
                b[nt][0] = Bu[(kb + tig    ) * BSTR + bc];
                b[nt][1] = Bu[(kb + tig + 4) * BSTR + bc];
            }
            #pragma unroll
            for (int mt = 0; mt < 4; mt++)
                #pragma unroll
                for (int nt = 0; nt < 4; nt++)
                    mma8(c[mt][nt], a[mt][0], a[mt][1], a[mt][2], a[mt][3],
                         b[nt][0], b[nt][1]);
        }
        __syncthreads();
    }

    // ---- epilogue ----
    #pragma unroll
    for (int mt = 0; mt < 4; mt++) {
        #pragma unroll
        for (int nt = 0; nt < 4; nt++) {
            int col = bn + wn * 32 + nt * 8 + tig * 2;
            float2 bi = make_float2(0.f, 0.f);
            if (BIAS) bi = *(const float2*)&bias[col];
            #pragma unroll
            for (int half = 0; half < 2; half++) {
                int row = bm + wm * 64 + mt * 16 + gid + half * 8;
                float2 v;
                v.x = c[mt][nt][half * 2 + 0] + bi.x;
                v.y = c[mt][nt][half * 2 + 1] + bi.y;
                if (RES) {
                    float2 r = *(const float2*)&Res[(size_t)row * N + col];
                    v.x += r.x; v.y += r.y;
                }
                *(float2*)&C[(size_t)row * N + col] = v;
                if (TOUT) {
                    float2 t; t.x = tanhf(v.x); t.y = tanhf(v.y);
                    *(float2*)&CT[(size_t)row * N + col] = t;
                }
            }
        }
    }
}

// ---------------------------------------------------------------------------
// LayerNorm: one block per row; optional tanh side-output
// ---------------------------------------------------------------------------
__global__ void __launch_bounds__(256) ln_kernel(
    const float* __restrict__ X, const float* __restrict__ g,
    const float* __restrict__ b, float* __restrict__ Y,
    float* __restrict__ YT, int N)
{
    int row = blockIdx.x;
    const float* x = X + (size_t)row * N;
    float s = 0.f, s2 = 0.f;
    for (int i = threadIdx.x; i < N; i += 256) {
        float v = x[i];
        s += v; s2 = fmaf(v, v, s2);
    }
    __shared__ float sh[64];
    for (int o = 16; o > 0; o >>= 1) {
        s  += __shfl_down_sync(0xffffffffu, s,  o);
        s2 += __shfl_down_sync(0xffffffffu, s2, o);
    }
    int wid = threadIdx.x >> 5, lane = threadIdx.x & 31;
    if (lane == 0) { sh[wid] = s; sh[wid + 32] = s2; }
    __syncthreads();
    if (threadIdx.x == 0) {
        float ts = 0.f, ts2 = 0.f;
        for (int w = 0; w < 8; w++) { ts += sh[w]; ts2 += sh[w + 32]; }
        float mu  = ts / N;
        float var = ts2 / N - mu * mu;
        sh[0] = mu; sh[1] = rsqrtf(var + 1e-5f);
    }
    __syncthreads();
    float mu = sh[0], rstd = sh[1];
    for (int i = threadIdx.x; i < N; i += 256) {
        float v = (x[i] - mu) * rstd * g[i] + b[i];
        Y[(size_t)row * N + i] = v;
        if (YT) YT[(size_t)row * N + i] = tanhf(v);
    }
}

// ---------------------------------------------------------------------------
// QBNN combine + LayerNorm + exact GELU (+ optional residual, tanh output)
// ---------------------------------------------------------------------------
__global__ void __launch_bounds__(256) qln_gelu_kernel(
    const float* __restrict__ HT, const float* __restrict__ DLT,
    const float* __restrict__ g,  const float* __restrict__ b,
    const float* __restrict__ Res, float* __restrict__ Y,
    float* __restrict__ YT, int N)
{
    extern __shared__ float rowbuf[];
    __shared__ float sh[64];
    int row = blockIdx.x;
    size_t base = (size_t)row * N;

    float s = 0.f, s2 = 0.f;
    for (int i = threadIdx.x; i < N; i += 256) {
        float ht = HT[base + i];
        float v  = fmaf(LAM_EFF * DLT[base + i], tanhf(ht), ht);
        rowbuf[i] = v;
        s += v; s2 = fmaf(v, v, s2);
    }
    for (int o = 16; o > 0; o >>= 1) {
        s  += __shfl_down_sync(0xffffffffu, s,  o);
        s2 += __shfl_down_sync(0xffffffffu, s2, o);
    }
    int wid = threadIdx.x >> 5, lane = threadIdx.x & 31;
    if (lane == 0) { sh[wid] = s; sh[wid + 32] = s2; }
    __syncthreads();
    if (threadIdx.x == 0) {
        float ts = 0.f, ts2 = 0.f;
        for (int w = 0; w < 8; w++) { ts += sh[w]; ts2 += sh[w + 32]; }
        float mu  = ts / N;
        float var = ts2 / N - mu * mu;
        sh[0] = mu; sh[1] = rsqrtf(var + 1e-5f);
    }
    __syncthreads();
    float mu = sh[0], rstd = sh[1];
    for (int i = threadIdx.x; i < N; i += 256) {
        float v  = (rowbuf[i] - mu) * rstd * g[i] + b[i];
        float ge = v * normcdff(v);
        float o  = Res ? Res[base + i] + ge : ge;
        Y[base + i] = o;
        if (YT) YT[base + i] = tanhf(o);
    }
}

// ---------------------------------------------------------------------------
// tQJ: per (b,h): tanh(Q[b,:,h]) @ J[h]
// ---------------------------------------------------------------------------
__global__ void __launch_bounds__(256) tqj_kernel(
    const float* __restrict__ Q, const float* __restrict__ J,
    float* __restrict__ Out)
{
    __shared__ __align__(16) float As[64][64];
    __shared__ __align__(16) float Js[64][64];
    int tid = threadIdx.x;
    int bh = blockIdx.x; int b = bh >> 4, h = bh & 15;
    int s0 = blockIdx.y << 6;

    #pragma unroll
    for (int i = 0; i < 4; i++) {
        int idx = tid + (i << 8);
        int r = idx >> 4, kq = (idx & 15) << 2;
        float4 v = *(const float4*)&Q[((size_t)(b * SS + s0 + r)) * DD + h * HD + kq];
        As[kq + 0][r] = tanhf(v.x); As[kq + 1][r] = tanhf(v.y);
        As[kq + 2][r] = tanhf(v.z); As[kq + 3][r] = tanhf(v.w);
        ((float4*)Js)[idx] = *(const float4*)&J[(size_t)h * HD * HD + idx * 4];
    }
    __syncthreads();

    int tx = tid & 15, ty = tid >> 4;
    float c[4][4] = {};
    #pragma unroll 8
    for (int kk = 0; kk < 64; kk++) {
        float a[4], bv[4];
        *(float4*)a  = *(const float4*)&As[kk][ty * 4];
        *(float4*)bv = *(const float4*)&Js[kk][tx * 4];
        #pragma unroll
        for (int i = 0; i < 4; i++)
            #pragma unroll
            for (int j = 0; j < 4; j++)
                c[i][j] = fmaf(a[i], bv[j], c[i][j]);
    }
    #pragma unroll
    for (int i = 0; i < 4; i++) {
        float4 v; v.x = c[i][0]; v.y = c[i][1]; v.z = c[i][2]; v.w = c[i][3];
        *(float4*)&Out[((size_t)(b * SS + s0 + ty * 4 + i)) * DD + h * HD + tx * 4] = v;
    }
}

// ---------------------------------------------------------------------------
// Flash attention with tanh-Hopfield score correction.
// ---------------------------------------------------------------------------
#define ATT_PAD 68
#define ATT_SMEM (3 * 64 * ATT_PAD * 4)

__global__ void __launch_bounds__(64) attn_kernel(
    const float* __restrict__ Q,  const float* __restrict__ K,
    const float* __restrict__ TK, const float* __restrict__ V,
    const float* __restrict__ TQJ, float* __restrict__ O,
    const float* __restrict__ lam_p)
{
    extern __shared__ float sm[];
    float* Ks  = sm;
    float* TKs = Ks  + 64 * ATT_PAD;
    float* Vs  = TKs + 64 * ATT_PAD;

    int tid = threadIdx.x;
    int bh = blockIdx.y; int b = bh >> 4, h = bh & 15;
    int q0 = blockIdx.x << 6;
    const float lam = __ldg(lam_p);

    float4 q[16], t[16];
    {
        size_t qrow = ((size_t)(b * SS + q0 + tid)) * DD + h * HD;
        #pragma unroll
        for (int d = 0; d < 16; d++) {
            q[d] = *(const float4*)&Q[qrow + 4 * d];
            t[d] = *(const float4*)&TQJ[qrow + 4 * d];
        }
    }

    float o[64];
    #pragma unroll
    for (int d = 0; d < 64; d++) o[d] = 0.f;
    float m = -1e30f, l = 0.f;

    for (int k0 = 0; k0 < SS; k0 += 64) {
        __syncthreads();
        #pragma unroll
        for (int i = 0; i < 16; i++) {
            int idx = tid + (i << 6);
            int r = idx >> 4, dq = (idx & 15) << 2;
            size_t ga = ((size_t)(b * SS + k0 + r)) * DD + h * HD + dq;
            *(float4*)&Ks [r * ATT_PAD + dq] = *(const float4*)&K [ga];
            *(float4*)&TKs[r * ATT_PAD + dq] = *(const float4*)&TK[ga];
            *(float4*)&Vs [r * ATT_PAD + dq] = *(const float4*)&V [ga];
        }
        __syncthreads();

        #pragma unroll 2
        for (int j = 0; j < 64; j++) {
            const float4* k4  = (const float4*)&Ks [j * ATT_PAD];
            const float4* tk4 = (const float4*)&TKs[j * ATT_PAD];
            float acc = 0.f, accd = 0.f;
            #pragma unroll
            for (int d = 0; d < 16; d++) {
                float4 a = q[d], c = k4[d];
                acc = fmaf(a.x, c.x, acc); acc = fmaf(a.y, c.y, acc);
                acc = fmaf(a.z, c.z, acc); acc = fmaf(a.w, c.w, acc);
                float4 e = t[d], f = tk4[d];
                accd = fmaf(e.x, f.x, accd); accd = fmaf(e.y, f.y, accd);
                accd = fmaf(e.z, f.z, accd); accd = fmaf(e.w, f.w, accd);
            }
            float sj = fmaf(lam, accd, acc * INV_SCALE);
            if (sj > m) {
                float corr = __expf(m - sj);
                l *= corr;
                #pragma unroll
                for (int d = 0; d < 64; d++) o[d] *= corr;
                m = sj;
            }
            float p = __expf(sj - m);
            l += p;
            const float4* v4 = (const float4*)&Vs[j * ATT_PAD];
            #pragma unroll
            for (int d = 0; d < 16; d++) {
                float4 v = v4[d];
                o[4 * d + 0] = fmaf(p, v.x, o[4 * d + 0]);
                o[4 * d + 1] = fmaf(p, v.y, o[4 * d + 1]);
                o[4 * d + 2] = fmaf(p, v.z, o[4 * d + 2]);
                o[4 * d + 3] = fmaf(p, v.w, o[4 * d + 3]);
            }
        }
    }

    float inv = 1.f / l;
    size_t ob = ((size_t)(b * SS + q0 + tid)) * DD + h * HD;
    #pragma unroll
    for (int d = 0; d < 16; d++) {
        float4 v;
        v.x = o[4 * d + 0] * inv; v.y = o[4 * d + 1] * inv;
        v.z = o[4 * d + 2] * inv; v.w = o[4 * d + 3] * inv;
        *(float4*)&O[ob + 4 * d] = v;
    }
}

// ---------------------------------------------------------------------------
// Host driver
// ---------------------------------------------------------------------------
static float* symaddr(const void* s)
{
    void* p = nullptr;
    cudaGetSymbolAddress(&p, s);
    return (float*)p;
}

extern "C" void kernel_launch(void* const* d_in, const int* in_sizes, int n_in,
                              void* d_out, int out_size)
{
    (void)in_sizes; (void)n_in; (void)out_size;

    const float* x    = (const float*)d_in[0];
    const float* wq   = (const float*)d_in[1];
    const float* bq   = (const float*)d_in[2];
    const float* wk   = (const float*)d_in[3];
    const float* bk   = (const float*)d_in[4];
    const float* wv   = (const float*)d_in[5];
    const float* bv   = (const float*)d_in[6];
    const float* wo   = (const float*)d_in[7];
    const float* bo   = (const float*)d_in[8];
    const float* Jat  = (const float*)d_in[9];
    const float* lam  = (const float*)d_in[10];
    const float* gat  = (const float*)d_in[11];
    const float* bat  = (const float*)d_in[12];
    const float* W1   = (const float*)d_in[13];
    const float* b1   = (const float*)d_in[14];
    const float* J1   = (const float*)d_in[15];
    const float* g1   = (const float*)d_in[17];
    const float* be1  = (const float*)d_in[18];
    const float* W2   = (const float*)d_in[19];
    const float* b2   = (const float*)d_in[20];
    const float* J2   = (const float*)d_in[21];
    const float* g2   = (const float*)d_in[23];
    const float* be2  = (const float*)d_in[24];
    const float* gf   = (const float*)d_in[25];
    const float* bf   = (const float*)d_in[26];
    float* out = (float*)d_out;

    float* p_xn   = symaddr(buf_xn);
    float* p_Q    = symaddr(buf_Q);
    float* p_K    = symaddr(buf_K);
    float* p_tK   = symaddr(buf_tK);
    float* p_V    = symaddr(buf_V);
    float* p_tQJ  = symaddr(buf_tQJ);
    float* p_ao   = symaddr(buf_ao);
    float* p_x1   = symaddr(buf_x1);
    float* p_th   = symaddr(buf_th);
    float* p_hhat = symaddr(buf_hhat);
    float* p_dlt  = symaddr(buf_dlt);
    float* p_h1   = symaddr(buf_h1);
    float* p_th1  = symaddr(buf_th1);

    cudaFuncSetAttribute(attn_kernel,
                         cudaFuncAttributeMaxDynamicSharedMemorySize, ATT_SMEM);
    cudaFuncSetAttribute(gemm_tf32_kernel<true, false, false>,
                         cudaFuncAttributeMaxDynamicSharedMemorySize, GEMM_SMEM);
    cudaFuncSetAttribute(gemm_tf32_kernel<true, false, true>,
                         cudaFuncAttributeMaxDynamicSharedMemorySize, GEMM_SMEM);
    cudaFuncSetAttribute(gemm_tf32_kernel<true, true, false>,
                         cudaFuncAttributeMaxDynamicSharedMemorySize, GEMM_SMEM);
    cudaFuncSetAttribute(gemm_tf32_kernel<false, false, false>,
                         cudaFuncAttributeMaxDynamicSharedMemorySize, GEMM_SMEM);

    // --- attention branch -------------------------------------------------
    ln_kernel<<<NT, 256>>>(x, gat, bat, p_xn, nullptr, DD);

    dim3 gProj(DD / BN, NT / BM);
    gemm_tf32_kernel<true, false, false><<<gProj, 256, GEMM_SMEM>>>(
        p_xn, wq, bq, nullptr, p_Q, nullptr, NT, DD, DD);
    gemm_tf32_kernel<true, false, true ><<<gProj, 256, GEMM_SMEM>>>(
        p_xn, wk, bk, nullptr, p_K, p_tK, NT, DD, DD);
    gemm_tf32_kernel<true, false, false><<<gProj, 256, GEMM_SMEM>>>(
        p_xn, wv, bv, nullptr, p_V, nullptr, NT, DD, DD);

    tqj_kernel<<<dim3(BB * HH, SS / 64), 256>>>(p_Q, Jat, p_tQJ);

    attn_kernel<<<dim3(SS / 64, BB * HH), 64, ATT_SMEM>>>(
        p_Q, p_K, p_tK, p_V, p_tQJ, p_ao, lam);

    gemm_tf32_kernel<true, true, false><<<gProj, 256, GEMM_SMEM>>>(
        p_ao, wo, bo, x, p_x1, nullptr, NT, DD, DD);

    // --- QBNN FFN layer 1 -------------------------------------------------
    ln_kernel<<<NT, 256>>>(p_x1, gf, bf, p_xn, p_th, DD);

    dim3 gF1(FFD / BN, NT / BM);
    gemm_tf32_kernel<true,  false, false><<<gF1, 256, GEMM_SMEM>>>(
        p_xn, W1, b1, nullptr, p_hhat, nullptr, NT, FFD, DD);
    gemm_tf32_kernel<false, false, false><<<gF1, 256, GEMM_SMEM>>>(
        p_th, J1, nullptr, nullptr, p_dlt, nullptr, NT, FFD, DD);

    qln_gelu_kernel<<<NT, 256, FFD * sizeof(float)>>>(
        p_hhat, p_dlt, g1, be1, nullptr, p_h1, p_th1, FFD);

    // --- QBNN FFN layer 2 -------------------------------------------------
    dim3 gF2(DD / BN, NT / BM);
    gemm_tf32_kernel<true,  false, false><<<gF2, 256, GEMM_SMEM>>>(
        p_h1, W2, b2, nullptr, p_hhat, nullptr, NT, DD, FFD);
    gemm_tf32_kernel<false, false, false><<<gF2, 256, GEMM_SMEM>>>(
        p_th1, J2, nullptr, nullptr, p_dlt, nullptr, NT, DD, FFD);

    qln_gelu_kernel<<<NT, 256, DD * sizeof(float)>>>(
        p_hhat, p_dlt, g2, be2, p_x1, out, nullptr, DD);
}

// round 4
// speedup vs baseline: 3.6030x; 1.5367x over previous
#include <cuda_runtime.h>
#include <cuda_bf16.h>
#include <math.h>
#include <stdint.h>

// ---------------------------------------------------------------------------
// Problem constants
// ---------------------------------------------------------------------------
#define BB   4
#define SS   1024
#define DD   1024
#define HH   16
#define HD   64
#define FFD  4096
#define NT   (BB*SS)
#define INV_SCALE 0.125f
#define LAM_EFF   0.5f

// ---------------------------------------------------------------------------
// Scratch (device globals)
// ---------------------------------------------------------------------------
__device__ float buf_xn  [NT*DD];
__device__ float buf_Q   [NT*DD];
__device__ float buf_K   [NT*DD];
__device__ float buf_tK  [NT*DD];
__device__ float buf_V   [NT*DD];
__device__ float buf_tQJ [NT*DD];
__device__ float buf_ao  [NT*DD];
__device__ float buf_x1  [NT*DD];
__device__ float buf_th  [NT*DD];
__device__ float buf_hhat[NT*FFD];
__device__ float buf_dlt [NT*FFD];
__device__ float buf_h1  [NT*FFD];
__device__ float buf_th1 [NT*FFD];

// ---------------------------------------------------------------------------
// Async-copy + mma helpers
// ---------------------------------------------------------------------------
__device__ __forceinline__ void cp16(uint32_t smem_dst, const void* gsrc)
{
    asm volatile("cp.async.cg.shared.global [%0], [%1], 16;\n"
                 :: "r"(smem_dst), "l"(gsrc));
}
__device__ __forceinline__ void cp_commit()
{
    asm volatile("cp.async.commit_group;\n");
}
template<int N> __device__ __forceinline__ void cp_wait()
{
    asm volatile("cp.async.wait_group %0;\n" :: "n"(N));
}

__device__ __forceinline__ void mma8(float* c,
    uint32_t a0, uint32_t a1, uint32_t a2, uint32_t a3,
    uint32_t b0, uint32_t b1)
{
    asm volatile(
        "mma.sync.aligned.m16n8k8.row.col.f32.tf32.tf32.f32 "
        "{%0,%1,%2,%3},{%4,%5,%6,%7},{%8,%9},{%0,%1,%2,%3};"
        : "+f"(c[0]), "+f"(c[1]), "+f"(c[2]), "+f"(c[3])
        : "r"(a0), "r"(a1), "r"(a2), "r"(a3), "r"(b0), "r"(b1));
}

// ---------------------------------------------------------------------------
// TF32 GEMM v3: 128x128x32 block, 3-stage cp.async, frag double-buffer.
// 8 warps (2 M x 4 N), warp tile 64x32 (4x4 m16n8k8).
// ---------------------------------------------------------------------------
#define BM 128
#define BN 128
#define BK 32
#define ASTR 36
#define BSTR 136
#define ASZ (BM*ASTR)
#define BSZ (BK*BSTR)
#define NSTG 3
#define GEMM_SMEM (NSTG*(ASZ + BSZ) * 4)   // 107520 bytes

template<bool BIAS, bool RES, bool TOUT>
__global__ void __launch_bounds__(256) gemm_tf32_kernel(
    const float* __restrict__ A, const float* __restrict__ Bm,
    const float* __restrict__ bias, const float* __restrict__ Res,
    float* __restrict__ C, float* __restrict__ CT,
    int M, int N, int K)
{
    extern __shared__ float smem[];
    float* As = smem;
    float* Bs = smem + NSTG * ASZ;
    const uint32_t smem_u = (uint32_t)__cvta_generic_to_shared(smem);
    const uint32_t As_u = smem_u;
    const uint32_t Bs_u = smem_u + NSTG * ASZ * 4;

    const int tid = threadIdx.x;
    const int bn = blockIdx.x * BN, bm = blockIdx.y * BM;
    const int wid = tid >> 5, lane = tid & 31;
    const int wm = wid & 1, wn = wid >> 1;
    const int gid = lane >> 2, tig = lane & 3;

    float c[4][4][4] = {};

    auto load_stage = [&](int k0, int st) {
        uint32_t a_base = As_u + st * ASZ * 4;
        uint32_t b_base = Bs_u + st * BSZ * 4;
        #pragma unroll
        for (int i = 0; i < 4; i++) {
            int idx = tid + (i << 8);
            int r = idx >> 3, cq = (idx & 7) << 2;
            cp16(a_base + (r * ASTR + cq) * 4,
                 &A[(size_t)(bm + r) * K + k0 + cq]);
        }
        #pragma unroll
        for (int i = 0; i < 4; i++) {
            int idx = tid + (i << 8);
            int r = idx >> 5, cq = (idx & 31) << 2;
            cp16(b_base + (r * BSTR + cq) * 4,
                 &Bm[(size_t)(k0 + r) * N + bn + cq]);
        }
        cp_commit();
    };

    const int KT = K / BK;
    load_stage(0, 0);
    load_stage(BK, 1);

    uint32_t a[2][4][4], b[2][4][2];
    const uint32_t* Au;
    const uint32_t* Bu;

    auto ldfrag = [&](int kk, int buf) {
        int kb = kk << 3;
        #pragma unroll
        for (int mt = 0; mt < 4; mt++) {
            int ar = wm * 64 + mt * 16 + gid;
            a[buf][mt][0] = Au[(ar    ) * ASTR + kb + tig];
            a[buf][mt][1] = Au[(ar + 8) * ASTR + kb + tig];
            a[buf][mt][2] = Au[(ar    ) * ASTR + kb + tig + 4];
            a[buf][mt][3] = Au[(ar + 8) * ASTR + kb + tig + 4];
        }
        #pragma unroll
        for (int nt = 0; nt < 4; nt++) {
            int bc = wn * 32 + nt * 8 + gid;
            b[buf][nt][0] = Bu[(kb + tig    ) * BSTR + bc];
            b[buf][nt][1] = Bu[(kb + tig + 4) * BSTR + bc];
        }
    };

    for (int kt = 0; kt < KT; kt++) {
        if (kt + 1 < KT) cp_wait<1>(); else cp_wait<0>();
        __syncthreads();
        if (kt + 2 < KT) load_stage((kt + 2) * BK, (kt + 2) % NSTG);

        int st = kt % NSTG;
        Au = (const uint32_t*)(As + st * ASZ);
        Bu = (const uint32_t*)(Bs + st * BSZ);

        ldfrag(0, 0);
        #pragma unroll
        for (int kk = 0; kk < 4; kk++) {
            if (kk < 3) ldfrag(kk + 1, (kk + 1) & 1);
            int cb = kk & 1;
            #pragma unroll
            for (int mt = 0; mt < 4; mt++)
                #pragma unroll
                for (int nt = 0; nt < 4; nt++)
                    mma8(c[mt][nt], a[cb][mt][0], a[cb][mt][1],
                         a[cb][mt][2], a[cb][mt][3],
                         b[cb][nt][0], b[cb][nt][1]);
        }
        __syncthreads();
    }

    #pragma unroll
    for (int mt = 0; mt < 4; mt++) {
        #pragma unroll
        for (int nt = 0; nt < 4; nt++) {
            int col = bn + wn * 32 + nt * 8 + tig * 2;
            float2 bi = make_float2(0.f, 0.f);
            if (BIAS) bi = *(const float2*)&bias[col];
            #pragma unroll
            for (int half = 0; half < 2; half++) {
                int row = bm + wm * 64 + mt * 16 + gid + half * 8;
                float2 v;
                v.x = c[mt][nt][half * 2 + 0] + bi.x;
                v.y = c[mt][nt][half * 2 + 1] + bi.y;
                if (RES) {
                    float2 r = *(const float2*)&Res[(size_t)row * N + col];
                    v.x += r.x; v.y += r.y;
                }
                *(float2*)&C[(size_t)row * N + col] = v;
                if (TOUT) {
                    float2 t; t.x = tanhf(v.x); t.y = tanhf(v.y);
                    *(float2*)&CT[(size_t)row * N + col] = t;
                }
            }
        }
    }
}

// ---------------------------------------------------------------------------
// Tensor-core flash attention with tanh-Hopfield correction.
// Block: 128 threads (4 warps), 64 queries; iterate 64-key tiles.
// All tiles natural [token][d] layout, row pad 68 (conflict-free frags).
// ---------------------------------------------------------------------------
#define AT_STR 68
#define ATT_SMEM (6 * 64 * AT_STR * 4)   // Q,T,P,K,tK,V = 104448 B

__global__ void __launch_bounds__(128) attn_mma_kernel(
    const float* __restrict__ Q,  const float* __restrict__ K,
    const float* __restrict__ TK, const float* __restrict__ V,
    const float* __restrict__ TQJ, float* __restrict__ O,
    const float* __restrict__ lam_p)
{
    extern __shared__ float sm[];
    float* Qs  = sm;
    float* Ts  = Qs + 64 * AT_STR;
    float* Ps  = Ts + 64 * AT_STR;
    float* Ks  = Ps + 64 * AT_STR;
    float* tKs = Ks + 64 * AT_STR;
    float* Vs  = tKs + 64 * AT_STR;
    const uint32_t smem_u = (uint32_t)__cvta_generic_to_shared(sm);
    const uint32_t Qs_u  = smem_u;
    const uint32_t Ts_u  = Qs_u + 64 * AT_STR * 4;
    const uint32_t Ks_u  = Ts_u + 2 * 64 * AT_STR * 4;
    const uint32_t tKs_u = Ks_u + 64 * AT_STR * 4;
    const uint32_t Vs_u  = tKs_u + 64 * AT_STR * 4;

    const int tid = threadIdx.x;
    const int wid = tid >> 5, lane = tid & 31;
    const int gid = lane >> 2, tig = lane & 3;
    const int mrow = wid * 16;
    const int bh = blockIdx.y, b = bh >> 4, h = bh & 15;
    const int q0 = blockIdx.x << 6;
    const float lam = __ldg(lam_p);

    // Stage Q and tQJ tiles (once)
    #pragma unroll
    for (int i = tid; i < 1024; i += 128) {
        int r = i >> 4, c = (i & 15) << 2;
        size_t g = ((size_t)(b * SS + q0 + r)) * DD + h * HD + c;
        cp16(Qs_u + (r * AT_STR + c) * 4, &Q[g]);
        cp16(Ts_u + (r * AT_STR + c) * 4, &TQJ[g]);
    }
    cp_commit();

    float m0 = -1e30f, m1 = -1e30f, l0 = 0.f, l1 = 0.f;
    float o[8][4] = {};

    for (int k0 = 0; k0 < SS; k0 += 64) {
        __syncthreads();           // previous tile fully consumed
        #pragma unroll
        for (int i = tid; i < 1024; i += 128) {
            int r = i >> 4, c = (i & 15) << 2;
            size_t g = ((size_t)(b * SS + k0 + r)) * DD + h * HD + c;
            cp16(Ks_u  + (r * AT_STR + c) * 4, &K[g]);
            cp16(tKs_u + (r * AT_STR + c) * 4, &TK[g]);
            cp16(Vs_u  + (r * AT_STR + c) * 4, &V[g]);
        }
        cp_commit();
        cp_wait<0>();
        __syncthreads();

        // --- S = Q K^T, D = tQJ tanhK^T ---
        float cs[8][4] = {}, cd[8][4] = {};
        const uint32_t* Qu  = (const uint32_t*)Qs;
        const uint32_t* Tu  = (const uint32_t*)Ts;
        const uint32_t* Ku  = (const uint32_t*)Ks;
        const uint32_t* tKu = (const uint32_t*)tKs;
        #pragma unroll
        for (int kg = 0; kg < 8; kg++) {
            int kb = kg << 3;
            uint32_t aq[4], at[4];
            aq[0] = Qu[(mrow + gid    ) * AT_STR + kb + tig];
            aq[1] = Qu[(mrow + gid + 8) * AT_STR + kb + tig];
            aq[2] = Qu[(mrow + gid    ) * AT_STR + kb + tig + 4];
            aq[3] = Qu[(mrow + gid + 8) * AT_STR + kb + tig + 4];
            at[0] = Tu[(mrow + gid    ) * AT_STR + kb + tig];
            at[1] = Tu[(mrow + gid + 8) * AT_STR + kb + tig];
            at[2] = Tu[(mrow + gid    ) * AT_STR + kb + tig + 4];
            at[3] = Tu[(mrow + gid + 8) * AT_STR + kb + tig + 4];
            #pragma unroll
            for (int nt = 0; nt < 8; nt++) {
                int bc = nt * 8 + gid;
                uint32_t b0 = Ku[bc * AT_STR + kb + tig];
                uint32_t b1 = Ku[bc * AT_STR + kb + tig + 4];
                mma8(cs[nt], aq[0], aq[1], aq[2], aq[3], b0, b1);
                uint32_t d0 = tKu[bc * AT_STR + kb + tig];
                uint32_t d1 = tKu[bc * AT_STR + kb + tig + 4];
                mma8(cd[nt], at[0], at[1], at[2], at[3], d0, d1);
            }
        }

        // --- scores + online softmax ---
        float s[8][4];
        float mx0 = -1e30f, mx1 = -1e30f;
        #pragma unroll
        for (int nt = 0; nt < 8; nt++) {
            #pragma unroll
            for (int e = 0; e < 4; e++)
                s[nt][e] = fmaf(lam, cd[nt][e], cs[nt][e] * INV_SCALE);
            mx0 = fmaxf(mx0, fmaxf(s[nt][0], s[nt][1]));
            mx1 = fmaxf(mx1, fmaxf(s[nt][2], s[nt][3]));
        }
        mx0 = fmaxf(mx0, __shfl_xor_sync(0xffffffffu, mx0, 1));
        mx0 = fmaxf(mx0, __shfl_xor_sync(0xffffffffu, mx0, 2));
        mx1 = fmaxf(mx1, __shfl_xor_sync(0xffffffffu, mx1, 1));
        mx1 = fmaxf(mx1, __shfl_xor_sync(0xffffffffu, mx1, 2));
        float mn0 = fmaxf(m0, mx0), mn1 = fmaxf(m1, mx1);
        float corr0 = __expf(m0 - mn0), corr1 = __expf(m1 - mn1);
        m0 = mn0; m1 = mn1;
        l0 *= corr0; l1 *= corr1;

        float sum0 = 0.f, sum1 = 0.f;
        #pragma unroll
        for (int nt = 0; nt < 8; nt++) {
            float p00 = __expf(s[nt][0] - mn0);
            float p01 = __expf(s[nt][1] - mn0);
            float p10 = __expf(s[nt][2] - mn1);
            float p11 = __expf(s[nt][3] - mn1);
            sum0 += p00 + p01; sum1 += p10 + p11;
            int col = nt * 8 + tig * 2;
            *(float2*)&Ps[(mrow + gid    ) * AT_STR + col] = make_float2(p00, p01);
            *(float2*)&Ps[(mrow + gid + 8) * AT_STR + col] = make_float2(p10, p11);
        }
        sum0 += __shfl_xor_sync(0xffffffffu, sum0, 1);
        sum0 += __shfl_xor_sync(0xffffffffu, sum0, 2);
        sum1 += __shfl_xor_sync(0xffffffffu, sum1, 1);
        sum1 += __shfl_xor_sync(0xffffffffu, sum1, 2);
        l0 += sum0; l1 += sum1;

        #pragma unroll
        for (int nt = 0; nt < 8; nt++) {
            o[nt][0] *= corr0; o[nt][1] *= corr0;
            o[nt][2] *= corr1; o[nt][3] *= corr1;
        }
        __syncwarp();

        // --- O += P V ---
        const uint32_t* Pu = (const uint32_t*)Ps;
        const uint32_t* Vu = (const uint32_t*)Vs;
        #pragma unroll
        for (int kg = 0; kg < 8; kg++) {
            int kb = kg << 3;
            uint32_t ap[4];
            ap[0] = Pu[(mrow + gid    ) * AT_STR + kb + tig];
            ap[1] = Pu[(mrow + gid + 8) * AT_STR + kb + tig];
            ap[2] = Pu[(mrow + gid    ) * AT_STR + kb + tig + 4];
            ap[3] = Pu[(mrow + gid + 8) * AT_STR + kb + tig + 4];
            #pragma unroll
            for (int nt = 0; nt < 8; nt++) {
                int bc = nt * 8 + gid;
                uint32_t b0 = Vu[(kb + tig    ) * AT_STR + bc];
                uint32_t b1 = Vu[(kb + tig + 4) * AT_STR + bc];
                mma8(o[nt], ap[0], ap[1], ap[2], ap[3], b0, b1);
            }
        }
    }

    float inv0 = 1.f / l0, inv1 = 1.f / l1;
    int row0 = q0 + mrow + gid, row1 = row0 + 8;
    #pragma unroll
    for (int nt = 0; nt < 8; nt++) {
        int col = nt * 8 + tig * 2;
        *(float2*)&O[((size_t)(b * SS + row0)) * DD + h * HD + col] =
            make_float2(o[nt][0] * inv0, o[nt][1] * inv0);
        *(float2*)&O[((size_t)(b * SS + row1)) * DD + h * HD + col] =
            make_float2(o[nt][2] * inv1, o[nt][3] * inv1);
    }
}

// ---------------------------------------------------------------------------
// LayerNorm: one block per row; optional tanh side-output
// ---------------------------------------------------------------------------
__global__ void __launch_bounds__(256) ln_kernel(
    const float* __restrict__ X, const float* __restrict__ g,
    const float* __restrict__ b, float* __restrict__ Y,
    float* __restrict__ YT, int N)
{
    int row = blockIdx.x;
    const float* x = X + (size_t)row * N;
    float s = 0.f, s2 = 0.f;
    for (int i = threadIdx.x; i < N; i += 256) {
        float v = x[i];
        s += v; s2 = fmaf(v, v, s2);
    }
    __shared__ float sh[64];
    for (int o = 16; o > 0; o >>= 1) {
        s  += __shfl_down_sync(0xffffffffu, s,  o);
        s2 += __shfl_down_sync(0xffffffffu, s2, o);
    }
    int wid = threadIdx.x >> 5, lane = threadIdx.x & 31;
    if (lane == 0) { sh[wid] = s; sh[wid + 32] = s2; }
    __syncthreads();
    if (threadIdx.x == 0) {
        float ts = 0.f, ts2 = 0.f;
        for (int w = 0; w < 8; w++) { ts += sh[w]; ts2 += sh[w + 32]; }
        float mu  = ts / N;
        float var = ts2 / N - mu * mu;
        sh[0] = mu; sh[1] = rsqrtf(var + 1e-5f);
    }
    __syncthreads();
    float mu = sh[0], rstd = sh[1];
    for (int i = threadIdx.x; i < N; i += 256) {
        float v = (x[i] - mu) * rstd * g[i] + b[i];
        Y[(size_t)row * N + i] = v;
        if (YT) YT[(size_t)row * N + i] = tanhf(v);
    }
}

// ---------------------------------------------------------------------------
// QBNN combine + LayerNorm + exact GELU (+ optional residual, tanh output)
// ---------------------------------------------------------------------------
__global__ void __launch_bounds__(256) qln_gelu_kernel(
    const float* __restrict__ HT, const float* __restrict__ DLT,
    const float* __restrict__ g,  const float* __restrict__ b,
    const float* __restrict__ Res, float* __restrict__ Y,
    float* __restrict__ YT, int N)
{
    extern __shared__ float rowbuf[];
    __shared__ float sh[64];
    int row = blockIdx.x;
    size_t base = (size_t)row * N;

    float s = 0.f, s2 = 0.f;
    for (int i = threadIdx.x; i < N; i += 256) {
        float ht = HT[base + i];
        float v  = fmaf(LAM_EFF * DLT[base + i], tanhf(ht), ht);
        rowbuf[i] = v;
        s += v; s2 = fmaf(v, v, s2);
    }
    for (int o = 16; o > 0; o >>= 1) {
        s  += __shfl_down_sync(0xffffffffu, s,  o);
        s2 += __shfl_down_sync(0xffffffffu, s2, o);
    }
    int wid = threadIdx.x >> 5, lane = threadIdx.x & 31;
    if (lane == 0) { sh[wid] = s; sh[wid + 32] = s2; }
    __syncthreads();
    if (threadIdx.x == 0) {
        float ts = 0.f, ts2 = 0.f;
        for (int w = 0; w < 8; w++) { ts += sh[w]; ts2 += sh[w + 32]; }
        float mu  = ts / N;
        float var = ts2 / N - mu * mu;
        sh[0] = mu; sh[1] = rsqrtf(var + 1e-5f);
    }
    __syncthreads();
    float mu = sh[0], rstd = sh[1];
    for (int i = threadIdx.x; i < N; i += 256) {
        float v  = (rowbuf[i] - mu) * rstd * g[i] + b[i];
        float ge = v * normcdff(v);
        float o  = Res ? Res[base + i] + ge : ge;
        Y[base + i] = o;
        if (YT) YT[base + i] = tanhf(o);
    }
}

// ---------------------------------------------------------------------------
// tQJ: per (b,h): tanh(Q[b,:,h]) @ J[h]
// ---------------------------------------------------------------------------
__global__ void __launch_bounds__(256) tqj_kernel(
    const float* __restrict__ Q, const float* __restrict__ J,
    float* __restrict__ Out)
{
    __shared__ __align__(16) float As[64][64];
    __shared__ __align__(16) float Js[64][64];
    int tid = threadIdx.x;
    int bh = blockIdx.x; int b = bh >> 4, h = bh & 15;
    int s0 = blockIdx.y << 6;

    #pragma unroll
    for (int i = 0; i < 4; i++) {
        int idx = tid + (i << 8);
        int r = idx >> 4, kq = (idx & 15) << 2;
        float4 v = *(const float4*)&Q[((size_t)(b * SS + s0 + r)) * DD + h * HD + kq];
        As[kq + 0][r] = tanhf(v.x); As[kq + 1][r] = tanhf(v.y);
        As[kq + 2][r] = tanhf(v.z); As[kq + 3][r] = tanhf(v.w);
        ((float4*)Js)[idx] = *(const float4*)&J[(size_t)h * HD * HD + idx * 4];
    }
    __syncthreads();

    int tx = tid & 15, ty = tid >> 4;
    float c[4][4] = {};
    #pragma unroll 8
    for (int kk = 0; kk < 64; kk++) {
        float a[4], bv[4];
        *(float4*)a  = *(const float4*)&As[kk][ty * 4];
        *(float4*)bv = *(const float4*)&Js[kk][tx * 4];
        #pragma unroll
        for (int i = 0; i < 4; i++)
            #pragma unroll
            for (int j = 0; j < 4; j++)
                c[i][j] = fmaf(a[i], bv[j], c[i][j]);
    }
    #pragma unroll
    for (int i = 0; i < 4; i++) {
        float4 v; v.x = c[i][0]; v.y = c[i][1]; v.z = c[i][2]; v.w = c[i][3];
        *(float4*)&Out[((size_t)(b * SS + s0 + ty * 4 + i)) * DD + h * HD + tx * 4] = v;
    }
}

// ---------------------------------------------------------------------------
// Host driver
// ---------------------------------------------------------------------------
static float* symaddr(const void* s)
{
    void* p = nullptr;
    cudaGetSymbolAddress(&p, s);
    return (float*)p;
}

extern "C" void kernel_launch(void* const* d_in, const int* in_sizes, int n_in,
                              void* d_out, int out_size)
{
    (void)in_sizes; (void)n_in; (void)out_size;

    const float* x    = (const float*)d_in[0];
    const float* wq   = (const float*)d_in[1];
    const float* bq   = (const float*)d_in[2];
    const float* wk   = (const float*)d_in[3];
    const float* bk   = (const float*)d_in[4];
    const float* wv   = (const float*)d_in[5];
    const float* bv   = (const float*)d_in[6];
    const float* wo   = (const float*)d_in[7];
    const float* bo   = (const float*)d_in[8];
    const float* Jat  = (const float*)d_in[9];
    const float* lam  = (const float*)d_in[10];
    const float* gat  = (const float*)d_in[11];
    const float* bat  = (const float*)d_in[12];
    const float* W1   = (const float*)d_in[13];
    const float* b1   = (const float*)d_in[14];
    const float* J1   = (const float*)d_in[15];
    const float* g1   = (const float*)d_in[17];
    const float* be1  = (const float*)d_in[18];
    const float* W2   = (const float*)d_in[19];
    const float* b2   = (const float*)d_in[20];
    const float* J2   = (const float*)d_in[21];
    const float* g2   = (const float*)d_in[23];
    const float* be2  = (const float*)d_in[24];
    const float* gf   = (const float*)d_in[25];
    const float* bf   = (const float*)d_in[26];
    float* out = (float*)d_out;

    float* p_xn   = symaddr(buf_xn);
    float* p_Q    = symaddr(buf_Q);
    float* p_K    = symaddr(buf_K);
    float* p_tK   = symaddr(buf_tK);
    float* p_V    = symaddr(buf_V);
    float* p_tQJ  = symaddr(buf_tQJ);
    float* p_ao   = symaddr(buf_ao);
    float* p_x1   = symaddr(buf_x1);
    float* p_th   = symaddr(buf_th);
    float* p_hhat = symaddr(buf_hhat);
    float* p_dlt  = symaddr(buf_dlt);
    float* p_h1   = symaddr(buf_h1);
    float* p_th1  = symaddr(buf_th1);

    cudaFuncSetAttribute(attn_mma_kernel,
                         cudaFuncAttributeMaxDynamicSharedMemorySize, ATT_SMEM);
    cudaFuncSetAttribute(gemm_tf32_kernel<true, false, false>,
                         cudaFuncAttributeMaxDynamicSharedMemorySize, GEMM_SMEM);
    cudaFuncSetAttribute(gemm_tf32_kernel<true, false, true>,
                         cudaFuncAttributeMaxDynamicSharedMemorySize, GEMM_SMEM);
    cudaFuncSetAttribute(gemm_tf32_kernel<true, true, false>,
                         cudaFuncAttributeMaxDynamicSharedMemorySize, GEMM_SMEM);
    cudaFuncSetAttribute(gemm_tf32_kernel<false, false, false>,
                         cudaFuncAttributeMaxDynamicSharedMemorySize, GEMM_SMEM);

    // --- attention branch -------------------------------------------------
    ln_kernel<<<NT, 256>>>(x, gat, bat, p_xn, nullptr, DD);

    dim3 gProj(DD / BN, NT / BM);
    gemm_tf32_kernel<true, false, false><<<gProj, 256, GEMM_SMEM>>>(
        p_xn, wq, bq, nullptr, p_Q, nullptr, NT, DD, DD);
    gemm_tf32_kernel<true, false, true ><<<gProj, 256, GEMM_SMEM>>>(
        p_xn, wk, bk, nullptr, p_K, p_tK, NT, DD, DD);
    gemm_tf32_kernel<true, false, false><<<gProj, 256, GEMM_SMEM>>>(
        p_xn, wv, bv, nullptr, p_V, nullptr, NT, DD, DD);

    tqj_kernel<<<dim3(BB * HH, SS / 64), 256>>>(p_Q, Jat, p_tQJ);

    attn_mma_kernel<<<dim3(SS / 64, BB * HH), 128, ATT_SMEM>>>(
        p_Q, p_K, p_tK, p_V, p_tQJ, p_ao, lam);

    gemm_tf32_kernel<true, true, false><<<gProj, 256, GEMM_SMEM>>>(
        p_ao, wo, bo, x, p_x1, nullptr, NT, DD, DD);

    // --- QBNN FFN layer 1 -------------------------------------------------
    ln_kernel<<<NT, 256>>>(p_x1, gf, bf, p_xn, p_th, DD);

    dim3 gF1(FFD / BN, NT / BM);
    gemm_tf32_kernel<true,  false, false><<<gF1, 256, GEMM_SMEM>>>(
        p_xn, W1, b1, nullptr, p_hhat, nullptr, NT, FFD, DD);
    gemm_tf32_kernel<false, false, false><<<gF1, 256, GEMM_SMEM>>>(
        p_th, J1, nullptr, nullptr, p_dlt, nullptr, NT, FFD, DD);

    qln_gelu_kernel<<<NT, 256, FFD * sizeof(float)>>>(
        p_hhat, p_dlt, g1, be1, nullptr, p_h1, p_th1, FFD);

    // --- QBNN FFN layer 2 -------------------------------------------------
    dim3 gF2(DD / BN, NT / BM);
    gemm_tf32_kernel<true,  false, false><<<gF2, 256, GEMM_SMEM>>>(
        p_h1, W2, b2, nullptr, p_hhat, nullptr, NT, DD, FFD);
    gemm_tf32_kernel<false, false, false><<<gF2, 256, GEMM_SMEM>>>(
        p_th1, J2, nullptr, nullptr, p_dlt, nullptr, NT, DD, FFD);

    qln_gelu_kernel<<<NT, 256, DD * sizeof(float)>>>(
        p_hhat, p_dlt, g2, be2, p_x1, out, nullptr, DD);
}